// round 14
// baseline (speedup 1.0000x reference)
#include <cuda_runtime.h>
#include <cuda_fp16.h>
#include <cstdint>

#define NN 100000
#define NE 1600000
#define IN_CH 256
#define HID 128
#define OUT_CH 64

#define SCH 1024                       // elements per scan chunk
#define NCHK ((NN + SCH - 1) / SCH)    // 98 chunks

#define NCH 4                          // row chunks for agg/MLP pipeline
#define CROWS 25088                    // 196 blocks * 128 rows

// Scratch (device globals: allocation-free per harness rules)
__device__ __align__(16) __half g_h[(size_t)NN * HID];   // 25.6 MB (fp16)
__device__ int   g_deg[NN];
__device__ int   g_row_off[NN + 1];
__device__ int   g_cursor[NN];
__device__ int   g_csr_src[NE];
__device__ int   g_part[NCHK];
__device__ __align__(16) float g_W12[HID * OUT_CH];      // W1 @ W2, [k][o]

// ---------------------------------------------------------------------------
// prep: W12 = W1 @ W2  (fp32; re-association error ~1e-7 rel; proven R11)
// ---------------------------------------------------------------------------
__global__ void prep_w12(const float* __restrict__ W1, const float* __restrict__ W2)
{
    int i = blockIdx.x * blockDim.x + threadIdx.x;   // HID*OUT_CH = 8192
    if (i >= HID * OUT_CH) return;
    int k = i >> 6, o = i & 63;
    float s = 0.f;
#pragma unroll 8
    for (int j = 0; j < HID; j++) s += W1[k * HID + j] * W2[j * OUT_CH + o];
    g_W12[i] = s;
}

// ---------------------------------------------------------------------------
// SGEMM: C[M,N] = A[M,K] @ B[K,N].  BM=128, BK=8, 256 threads, 8x(N/16) tile.
// HALF_OUT: store C as fp16 (for h); else fp32.
// ---------------------------------------------------------------------------
template <int K, int N, bool HALF_OUT>
__global__ void __launch_bounds__(256) sgemm_kernel(const float* __restrict__ A,
                                                    const float* __restrict__ B,
                                                    float* __restrict__ C,
                                                    __half* __restrict__ Ch, int M)
{
    constexpr int BM = 128, BN = N, BK = 8;
    constexpr int TM = 8, TN = BN / 16;          // 8 or 4
    __shared__ float As[BK][BM];
    __shared__ float Bs[BK][BN];

    const int tid = threadIdx.x;
    const int tx = tid & 15;                     // col group
    const int ty = tid >> 4;                     // row group
    const int row0 = blockIdx.x * BM;

    float acc[TM][TN];
#pragma unroll
    for (int i = 0; i < TM; i++)
#pragma unroll
        for (int j = 0; j < TN; j++) acc[i][j] = 0.f;

    const int ar = tid >> 1;
    const int ak = (tid & 1) * 4;

    for (int k0 = 0; k0 < K; k0 += BK) {
        // Stage A tile (transposed into As[kk][row])
        {
            int gr = row0 + ar;
            float4 v = make_float4(0.f, 0.f, 0.f, 0.f);
            if (gr < M)
                v = *reinterpret_cast<const float4*>(&A[(size_t)gr * K + k0 + ak]);
            As[ak + 0][ar] = v.x;
            As[ak + 1][ar] = v.y;
            As[ak + 2][ar] = v.z;
            As[ak + 3][ar] = v.w;
        }
        // Stage B tile: BK*BN floats, float4 per thread
        {
            int idx = tid * 4;
            if (idx < BK * BN) {
                int kk = idx / BN, c = idx % BN;
                *reinterpret_cast<float4*>(&Bs[kk][c]) =
                    *reinterpret_cast<const float4*>(&B[(size_t)(k0 + kk) * N + c]);
            }
        }
        __syncthreads();

#pragma unroll
        for (int kk = 0; kk < BK; kk++) {
            float a[TM], b[TN];
            float4 a0 = *reinterpret_cast<const float4*>(&As[kk][ty * TM]);
            float4 a1 = *reinterpret_cast<const float4*>(&As[kk][ty * TM + 4]);
            a[0]=a0.x; a[1]=a0.y; a[2]=a0.z; a[3]=a0.w;
            a[4]=a1.x; a[5]=a1.y; a[6]=a1.z; a[7]=a1.w;
            float4 b0 = *reinterpret_cast<const float4*>(&Bs[kk][tx * TN]);
            b[0]=b0.x; b[1]=b0.y; b[2]=b0.z; b[3]=b0.w;
            if (TN == 8) {
                float4 b1 = *reinterpret_cast<const float4*>(&Bs[kk][tx * TN + 4]);
                b[4]=b1.x; b[5]=b1.y; b[6]=b1.z; b[7]=b1.w;
            }
#pragma unroll
            for (int i = 0; i < TM; i++)
#pragma unroll
                for (int j = 0; j < TN; j++)
                    acc[i][j] = fmaf(a[i], b[j], acc[i][j]);
        }
        __syncthreads();
    }

#pragma unroll
    for (int i = 0; i < TM; i++) {
        int gr = row0 + ty * TM + i;
        if (gr < M) {
            if constexpr (HALF_OUT) {
                __half2 p0 = __floats2half2_rn(acc[i][0], acc[i][1]);
                __half2 p1 = __floats2half2_rn(acc[i][2], acc[i][3]);
                __half2 p2 = __floats2half2_rn(acc[i][4], acc[i][5]);
                __half2 p3 = __floats2half2_rn(acc[i][6], acc[i][7]);
                uint4 pk;
                pk.x = *reinterpret_cast<uint32_t*>(&p0);
                pk.y = *reinterpret_cast<uint32_t*>(&p1);
                pk.z = *reinterpret_cast<uint32_t*>(&p2);
                pk.w = *reinterpret_cast<uint32_t*>(&p3);
                *reinterpret_cast<uint4*>(&Ch[(size_t)gr * N + tx * TN]) = pk;
            } else {
                float* cp = &C[(size_t)gr * N + tx * TN];
                *reinterpret_cast<float4*>(cp) =
                    make_float4(acc[i][0], acc[i][1], acc[i][2], acc[i][3]);
                if (TN == 8)
                    *reinterpret_cast<float4*>(cp + 4) =
                        make_float4(acc[i][4], acc[i][5], acc[i][6], acc[i][7]);
            }
        }
    }
}

// ---------------------------------------------------------------------------
// CSR build: histogram -> 3-phase parallel exclusive scan -> cursor fill
// ---------------------------------------------------------------------------
__global__ void hist_kernel(const int* __restrict__ dst)
{
    int stride = gridDim.x * blockDim.x;
    for (int e = blockIdx.x * blockDim.x + threadIdx.x; e < NE; e += stride)
        atomicAdd(&g_deg[dst[e]], 1);
}

__global__ void __launch_bounds__(256) scan_partial_kernel()
{
    __shared__ int red[8];
    int b = blockIdx.x, t = threadIdx.x;
    int base = b * SCH;
    int sum = 0;
#pragma unroll
    for (int q = 0; q < SCH / 256; q++) {
        int i = base + q * 256 + t;
        if (i < NN) sum += g_deg[i];
    }
    for (int o = 16; o > 0; o >>= 1) sum += __shfl_down_sync(0xffffffffu, sum, o);
    if ((t & 31) == 0) red[t >> 5] = sum;
    __syncthreads();
    if (t < 8) {
        int v = red[t];
        for (int o = 4; o > 0; o >>= 1) v += __shfl_down_sync(0xffu, v, o);
        if (t == 0) g_part[b] = v;
    }
}

__global__ void __launch_bounds__(128) scan_chunks_kernel()
{
    __shared__ int s[128];
    int t = threadIdx.x;
    int v = (t < NCHK) ? g_part[t] : 0;
    s[t] = v;
    __syncthreads();
#pragma unroll
    for (int o = 1; o < 128; o <<= 1) {
        int u = (t >= o) ? s[t - o] : 0;
        __syncthreads();
        s[t] += u;
        __syncthreads();
    }
    if (t < NCHK) g_part[t] = s[t] - v;     // exclusive chunk base
    if (t == 127) g_row_off[NN] = s[127];   // total (== NE)
}

__global__ void __launch_bounds__(256) scan_write_kernel()
{
    __shared__ int s[256];
    int b = blockIdx.x, t = threadIdx.x;
    int i0 = b * SCH + t * 4;

    int4 d = make_int4(0, 0, 0, 0);
    if (i0 < NN) d = *reinterpret_cast<const int4*>(&g_deg[i0]);  // NN % 4 == 0
    int tsum = d.x + d.y + d.z + d.w;

    s[t] = tsum;
    __syncthreads();
#pragma unroll
    for (int o = 1; o < 256; o <<= 1) {
        int u = (t >= o) ? s[t - o] : 0;
        __syncthreads();
        s[t] += u;
        __syncthreads();
    }
    int base = g_part[b] + s[t] - tsum;     // exclusive within chunk

    if (i0 < NN) {
        int4 ro, cu;
        ro.x = base;             cu.x = ro.x;
        ro.y = ro.x + d.x;       cu.y = ro.y;
        ro.z = ro.y + d.y;       cu.z = ro.z;
        ro.w = ro.z + d.z;       cu.w = ro.w;
        *reinterpret_cast<int4*>(&g_row_off[i0]) = ro;
        *reinterpret_cast<int4*>(&g_cursor[i0]) = cu;
    }
}

__global__ void fill_kernel(const int* __restrict__ src, const int* __restrict__ dst)
{
    int stride = gridDim.x * blockDim.x;
    for (int e = blockIdx.x * blockDim.x + threadIdx.x; e < NE; e += stride) {
        int pos = atomicAdd(&g_cursor[dst[e]], 1);
        g_csr_src[pos] = src[e];
    }
}

// ---------------------------------------------------------------------------
// Gather aggregation over node range [base, base+cnt): one warp per node;
// fp16 h rows, fp32 accumulation.
// ---------------------------------------------------------------------------
__global__ void agg_kernel(const float* __restrict__ bias, float* __restrict__ out1,
                           int base, int cnt)
{
    int w = (blockIdx.x * blockDim.x + threadIdx.x) >> 5;
    int lane = threadIdx.x & 31;
    if (w >= cnt) return;
    int node = base + w;

    const uint2* h2 = reinterpret_cast<const uint2*>(g_h);
    int s = g_row_off[node];
    int e = g_row_off[node + 1];

    float4 acc0 = make_float4(0.f, 0.f, 0.f, 0.f);
    float4 acc1 = make_float4(0.f, 0.f, 0.f, 0.f);
    int i = s;
    for (; i + 1 < e; i += 2) {
        int s0 = g_csr_src[i];
        int s1 = g_csr_src[i + 1];
        uint2 u0 = h2[(size_t)s0 * (HID / 4) + lane];
        uint2 u1 = h2[(size_t)s1 * (HID / 4) + lane];
        float2 a = __half22float2(*reinterpret_cast<__half2*>(&u0.x));
        float2 b = __half22float2(*reinterpret_cast<__half2*>(&u0.y));
        float2 c = __half22float2(*reinterpret_cast<__half2*>(&u1.x));
        float2 d = __half22float2(*reinterpret_cast<__half2*>(&u1.y));
        acc0.x += a.x; acc0.y += a.y; acc0.z += b.x; acc0.w += b.y;
        acc1.x += c.x; acc1.y += c.y; acc1.z += d.x; acc1.w += d.y;
    }
    if (i < e) {
        int s0 = g_csr_src[i];
        uint2 u0 = h2[(size_t)s0 * (HID / 4) + lane];
        float2 a = __half22float2(*reinterpret_cast<__half2*>(&u0.x));
        float2 b = __half22float2(*reinterpret_cast<__half2*>(&u0.y));
        acc0.x += a.x; acc0.y += a.y; acc0.z += b.x; acc0.w += b.y;
    }
    float4 bv = reinterpret_cast<const float4*>(bias)[lane];
    acc0.x += acc1.x + bv.x; acc0.y += acc1.y + bv.y;
    acc0.z += acc1.z + bv.z; acc0.w += acc1.w + bv.w;
    reinterpret_cast<float4*>(out1)[(size_t)node * (HID / 4) + lane] = acc0;
}

// ---------------------------------------------------------------------------
extern "C" void kernel_launch(void* const* d_in, const int* in_sizes, int n_in,
                              void* d_out, int out_size)
{
    const float* x   = (const float*)d_in[0];
    const int* edge  = (const int*)d_in[1];
    const float* Wg  = (const float*)d_in[2];
    const float* bg  = (const float*)d_in[3];
    const float* W1  = (const float*)d_in[4];
    const float* W2  = (const float*)d_in[5];
    const int* src = edge;
    const int* dst = edge + NE;

    float* out  = (float*)d_out;
    float* out1 = out;                                  // [NN, HID]
    float* out2 = out1 + (size_t)NN * HID;              // [NN, HID]
    float* out3 = out2 + (size_t)NN * HID;              // [NN, OUT_CH]

    __half* h = nullptr;
    cudaGetSymbolAddress((void**)&h, g_h);
    int* degPtr = nullptr;
    cudaGetSymbolAddress((void**)&degPtr, g_deg);
    float* w12 = nullptr;
    cudaGetSymbolAddress((void**)&w12, g_W12);

    // one-time streams + events (same DAG captured every call)
    static cudaStream_t s_side = nullptr, s_mlp = nullptr;
    static cudaEvent_t ev_fork = nullptr, ev_join = nullptr, ev_mlp_done = nullptr;
    static cudaEvent_t ev_agg[NCH];
    if (s_side == nullptr) {
        cudaStreamCreateWithFlags(&s_side, cudaStreamNonBlocking);
        cudaStreamCreateWithFlags(&s_mlp, cudaStreamNonBlocking);
        cudaEventCreateWithFlags(&ev_fork, cudaEventDisableTiming);
        cudaEventCreateWithFlags(&ev_join, cudaEventDisableTiming);
        cudaEventCreateWithFlags(&ev_mlp_done, cudaEventDisableTiming);
        for (int c = 0; c < NCH; c++)
            cudaEventCreateWithFlags(&ev_agg[c], cudaEventDisableTiming);
    }

    const int M = NN;
    const int MBLK = (M + 127) / 128;

    // fork: CSR build + W12 prep on side stream, concurrent with GEMM1
    cudaEventRecord(ev_fork, 0);
    cudaStreamWaitEvent(s_side, ev_fork, 0);

    prep_w12<<<(HID * OUT_CH + 255) / 256, 256, 0, s_side>>>(W1, W2);
    cudaMemsetAsync(degPtr, 0, NN * sizeof(int), s_side);
    hist_kernel<<<1024, 256, 0, s_side>>>(dst);
    scan_partial_kernel<<<NCHK, 256, 0, s_side>>>();
    scan_chunks_kernel<<<1, 128, 0, s_side>>>();
    scan_write_kernel<<<NCHK, 256, 0, s_side>>>();
    fill_kernel<<<1024, 256, 0, s_side>>>(src, dst);
    cudaEventRecord(ev_join, s_side);

    // main stream: GEMM1 (independent of CSR build)
    sgemm_kernel<IN_CH, HID, true><<<MBLK, 256>>>(x, Wg, nullptr, h, M);

    // join: agg needs both GEMM1 (h) and CSR (row_off/csr_src)
    cudaStreamWaitEvent(0, ev_join, 0);

    // pipelined agg (main) + per-chunk MLP (s_mlp)
    for (int c = 0; c < NCH; c++) {
        int base = c * CROWS;
        int cnt = (c == NCH - 1) ? (NN - base) : CROWS;
        agg_kernel<<<(cnt * 32 + 255) / 256, 256>>>(bg, out1, base, cnt);
        cudaEventRecord(ev_agg[c], 0);

        cudaStreamWaitEvent(s_mlp, ev_agg[c], 0);
        int cb = (cnt + 127) / 128;
        sgemm_kernel<HID, HID, false><<<cb, 256, 0, s_mlp>>>(
            out1 + (size_t)base * HID, W1, out2 + (size_t)base * HID, nullptr, cnt);
        sgemm_kernel<HID, OUT_CH, false><<<cb, 256, 0, s_mlp>>>(
            out1 + (size_t)base * HID, w12, out3 + (size_t)base * OUT_CH, nullptr, cnt);
    }
    cudaEventRecord(ev_mlp_done, s_mlp);
    cudaStreamWaitEvent(0, ev_mlp_done, 0);
}

// round 15
// speedup vs baseline: 1.1975x; 1.1975x over previous
#include <cuda_runtime.h>
#include <cuda_fp16.h>
#include <cstdint>

#define NN 100000
#define NE 1600000
#define IN_CH 256
#define HID 128
#define OUT_CH 64

#define SCH 1024                       // elements per scan chunk
#define NCHK ((NN + SCH - 1) / SCH)    // 98 chunks

// Scratch (device globals: allocation-free per harness rules)
__device__ __align__(16) __half g_h[(size_t)NN * HID];   // 25.6 MB (fp16)
__device__ int   g_deg[NN];
__device__ int   g_row_off[NN + 1];
__device__ int   g_cursor[NN];
__device__ int   g_csr_src[NE];
__device__ int   g_part[NCHK];
__device__ __align__(16) float g_W12[HID * OUT_CH];      // W1 @ W2, [k][o]

// ---------------------------------------------------------------------------
// prep: W12 = W1 @ W2  (fp32; re-association error ~1e-7 rel; proven R11)
// ---------------------------------------------------------------------------
__global__ void prep_w12(const float* __restrict__ W1, const float* __restrict__ W2)
{
    int i = blockIdx.x * blockDim.x + threadIdx.x;   // HID*OUT_CH = 8192
    if (i >= HID * OUT_CH) return;
    int k = i >> 6, o = i & 63;
    float s = 0.f;
#pragma unroll 8
    for (int j = 0; j < HID; j++) s += W1[k * HID + j] * W2[j * OUT_CH + o];
    g_W12[i] = s;
}

// ---------------------------------------------------------------------------
// SGEMM: C[M,N] = A[M,K] @ B[K,N].  BM=128, BK=16, 256 thr, 8x(N/16) tile.
// HALF_OUT: store C as fp16 (for h); else fp32.
// ---------------------------------------------------------------------------
template <int K, int N, bool HALF_OUT>
__global__ void __launch_bounds__(256) sgemm_kernel(const float* __restrict__ A,
                                                    const float* __restrict__ B,
                                                    float* __restrict__ C,
                                                    __half* __restrict__ Ch, int M)
{
    constexpr int BM = 128, BN = N, BK = 16;
    constexpr int TM = 8, TN = BN / 16;          // 8 or 4
    __shared__ float As[BK][BM];
    __shared__ float Bs[BK][BN];

    const int tid = threadIdx.x;
    const int tx = tid & 15;                     // col group
    const int ty = tid >> 4;                     // row group
    const int row0 = blockIdx.x * BM;

    float acc[TM][TN];
#pragma unroll
    for (int i = 0; i < TM; i++)
#pragma unroll
        for (int j = 0; j < TN; j++) acc[i][j] = 0.f;

    const int ar = tid >> 1;                 // A row handled by this thread
    const int ak = (tid & 1) * 8;            // k-offset (two float4)

    for (int k0 = 0; k0 < K; k0 += BK) {
        // Stage A tile (transposed into As[kk][row]); 2 x float4 per thread
        {
            int gr = row0 + ar;
            float4 v0 = make_float4(0.f, 0.f, 0.f, 0.f), v1 = v0;
            if (gr < M) {
                const float* gp = &A[(size_t)gr * K + k0 + ak];
                v0 = *reinterpret_cast<const float4*>(gp);
                v1 = *reinterpret_cast<const float4*>(gp + 4);
            }
            As[ak + 0][ar] = v0.x; As[ak + 1][ar] = v0.y;
            As[ak + 2][ar] = v0.z; As[ak + 3][ar] = v0.w;
            As[ak + 4][ar] = v1.x; As[ak + 5][ar] = v1.y;
            As[ak + 6][ar] = v1.z; As[ak + 7][ar] = v1.w;
        }
        // Stage B tile: BK*BN floats as float4
#pragma unroll
        for (int q = 0; q < (BK * BN) / 1024; q++) {
            int idx = (tid + q * 256) * 4;
            int kk = idx / BN, c = idx % BN;
            *reinterpret_cast<float4*>(&Bs[kk][c]) =
                *reinterpret_cast<const float4*>(&B[(size_t)(k0 + kk) * N + c]);
        }
        __syncthreads();

#pragma unroll
        for (int kk = 0; kk < BK; kk++) {
            float a[TM], b[TN];
            float4 a0 = *reinterpret_cast<const float4*>(&As[kk][ty * TM]);
            float4 a1 = *reinterpret_cast<const float4*>(&As[kk][ty * TM + 4]);
            a[0]=a0.x; a[1]=a0.y; a[2]=a0.z; a[3]=a0.w;
            a[4]=a1.x; a[5]=a1.y; a[6]=a1.z; a[7]=a1.w;
            float4 b0 = *reinterpret_cast<const float4*>(&Bs[kk][tx * TN]);
            b[0]=b0.x; b[1]=b0.y; b[2]=b0.z; b[3]=b0.w;
            if (TN == 8) {
                float4 b1 = *reinterpret_cast<const float4*>(&Bs[kk][tx * TN + 4]);
                b[4]=b1.x; b[5]=b1.y; b[6]=b1.z; b[7]=b1.w;
            }
#pragma unroll
            for (int i = 0; i < TM; i++)
#pragma unroll
                for (int j = 0; j < TN; j++)
                    acc[i][j] = fmaf(a[i], b[j], acc[i][j]);
        }
        __syncthreads();
    }

#pragma unroll
    for (int i = 0; i < TM; i++) {
        int gr = row0 + ty * TM + i;
        if (gr < M) {
            if constexpr (HALF_OUT) {
                __half2 p0 = __floats2half2_rn(acc[i][0], acc[i][1]);
                __half2 p1 = __floats2half2_rn(acc[i][2], acc[i][3]);
                __half2 p2 = __floats2half2_rn(acc[i][4], acc[i][5]);
                __half2 p3 = __floats2half2_rn(acc[i][6], acc[i][7]);
                uint4 pk;
                pk.x = *reinterpret_cast<uint32_t*>(&p0);
                pk.y = *reinterpret_cast<uint32_t*>(&p1);
                pk.z = *reinterpret_cast<uint32_t*>(&p2);
                pk.w = *reinterpret_cast<uint32_t*>(&p3);
                *reinterpret_cast<uint4*>(&Ch[(size_t)gr * N + tx * TN]) = pk;
            } else {
                float* cp = &C[(size_t)gr * N + tx * TN];
                *reinterpret_cast<float4*>(cp) =
                    make_float4(acc[i][0], acc[i][1], acc[i][2], acc[i][3]);
                if (TN == 8)
                    *reinterpret_cast<float4*>(cp + 4) =
                        make_float4(acc[i][4], acc[i][5], acc[i][6], acc[i][7]);
            }
        }
    }
}

// ---------------------------------------------------------------------------
// CSR build: histogram -> 3-phase parallel exclusive scan -> cursor fill
// ---------------------------------------------------------------------------
__global__ void hist_kernel(const int* __restrict__ dst)
{
    int stride = gridDim.x * blockDim.x;
    for (int e = blockIdx.x * blockDim.x + threadIdx.x; e < NE; e += stride)
        atomicAdd(&g_deg[dst[e]], 1);
}

__global__ void __launch_bounds__(256) scan_partial_kernel()
{
    __shared__ int red[8];
    int b = blockIdx.x, t = threadIdx.x;
    int base = b * SCH;
    int sum = 0;
#pragma unroll
    for (int q = 0; q < SCH / 256; q++) {
        int i = base + q * 256 + t;
        if (i < NN) sum += g_deg[i];
    }
    for (int o = 16; o > 0; o >>= 1) sum += __shfl_down_sync(0xffffffffu, sum, o);
    if ((t & 31) == 0) red[t >> 5] = sum;
    __syncthreads();
    if (t < 8) {
        int v = red[t];
        for (int o = 4; o > 0; o >>= 1) v += __shfl_down_sync(0xffu, v, o);
        if (t == 0) g_part[b] = v;
    }
}

__global__ void __launch_bounds__(128) scan_chunks_kernel()
{
    __shared__ int s[128];
    int t = threadIdx.x;
    int v = (t < NCHK) ? g_part[t] : 0;
    s[t] = v;
    __syncthreads();
#pragma unroll
    for (int o = 1; o < 128; o <<= 1) {
        int u = (t >= o) ? s[t - o] : 0;
        __syncthreads();
        s[t] += u;
        __syncthreads();
    }
    if (t < NCHK) g_part[t] = s[t] - v;     // exclusive chunk base
    if (t == 127) g_row_off[NN] = s[127];   // total (== NE)
}

__global__ void __launch_bounds__(256) scan_write_kernel()
{
    __shared__ int s[256];
    int b = blockIdx.x, t = threadIdx.x;
    int i0 = b * SCH + t * 4;

    int4 d = make_int4(0, 0, 0, 0);
    if (i0 < NN) d = *reinterpret_cast<const int4*>(&g_deg[i0]);  // NN % 4 == 0
    int tsum = d.x + d.y + d.z + d.w;

    s[t] = tsum;
    __syncthreads();
#pragma unroll
    for (int o = 1; o < 256; o <<= 1) {
        int u = (t >= o) ? s[t - o] : 0;
        __syncthreads();
        s[t] += u;
        __syncthreads();
    }
    int base = g_part[b] + s[t] - tsum;     // exclusive within chunk

    if (i0 < NN) {
        int4 ro, cu;
        ro.x = base;             cu.x = ro.x;
        ro.y = ro.x + d.x;       cu.y = ro.y;
        ro.z = ro.y + d.y;       cu.z = ro.z;
        ro.w = ro.z + d.z;       cu.w = ro.w;
        *reinterpret_cast<int4*>(&g_row_off[i0]) = ro;
        *reinterpret_cast<int4*>(&g_cursor[i0]) = cu;
    }
}

__global__ void fill_kernel(const int* __restrict__ src, const int* __restrict__ dst)
{
    int stride = gridDim.x * blockDim.x;
    for (int e = blockIdx.x * blockDim.x + threadIdx.x; e < NE; e += stride) {
        int pos = atomicAdd(&g_cursor[dst[e]], 1);
        g_csr_src[pos] = src[e];
    }
}

// ---------------------------------------------------------------------------
// Gather aggregation: one warp per node; fp16 h rows, fp32 accumulation.
// ---------------------------------------------------------------------------
__global__ void agg_kernel(const float* __restrict__ bias, float* __restrict__ out1)
{
    int warp = (blockIdx.x * blockDim.x + threadIdx.x) >> 5;
    int lane = threadIdx.x & 31;
    if (warp >= NN) return;

    const uint2* h2 = reinterpret_cast<const uint2*>(g_h);
    int s = g_row_off[warp];
    int e = g_row_off[warp + 1];

    float4 acc0 = make_float4(0.f, 0.f, 0.f, 0.f);
    float4 acc1 = make_float4(0.f, 0.f, 0.f, 0.f);
    int i = s;
    for (; i + 1 < e; i += 2) {
        int s0 = g_csr_src[i];
        int s1 = g_csr_src[i + 1];
        uint2 u0 = h2[(size_t)s0 * (HID / 4) + lane];
        uint2 u1 = h2[(size_t)s1 * (HID / 4) + lane];
        float2 a = __half22float2(*reinterpret_cast<__half2*>(&u0.x));
        float2 b = __half22float2(*reinterpret_cast<__half2*>(&u0.y));
        float2 c = __half22float2(*reinterpret_cast<__half2*>(&u1.x));
        float2 d = __half22float2(*reinterpret_cast<__half2*>(&u1.y));
        acc0.x += a.x; acc0.y += a.y; acc0.z += b.x; acc0.w += b.y;
        acc1.x += c.x; acc1.y += c.y; acc1.z += d.x; acc1.w += d.y;
    }
    if (i < e) {
        int s0 = g_csr_src[i];
        uint2 u0 = h2[(size_t)s0 * (HID / 4) + lane];
        float2 a = __half22float2(*reinterpret_cast<__half2*>(&u0.x));
        float2 b = __half22float2(*reinterpret_cast<__half2*>(&u0.y));
        acc0.x += a.x; acc0.y += a.y; acc0.z += b.x; acc0.w += b.y;
    }
    float4 bv = reinterpret_cast<const float4*>(bias)[lane];
    acc0.x += acc1.x + bv.x; acc0.y += acc1.y + bv.y;
    acc0.z += acc1.z + bv.z; acc0.w += acc1.w + bv.w;
    reinterpret_cast<float4*>(out1)[(size_t)warp * (HID / 4) + lane] = acc0;
}

// ---------------------------------------------------------------------------
extern "C" void kernel_launch(void* const* d_in, const int* in_sizes, int n_in,
                              void* d_out, int out_size)
{
    const float* x   = (const float*)d_in[0];
    const int* edge  = (const int*)d_in[1];
    const float* Wg  = (const float*)d_in[2];
    const float* bg  = (const float*)d_in[3];
    const float* W1  = (const float*)d_in[4];
    const float* W2  = (const float*)d_in[5];
    const int* src = edge;
    const int* dst = edge + NE;

    float* out  = (float*)d_out;
    float* out1 = out;                                  // [NN, HID]
    float* out2 = out1 + (size_t)NN * HID;              // [NN, HID]
    float* out3 = out2 + (size_t)NN * HID;              // [NN, OUT_CH]

    __half* h = nullptr;
    cudaGetSymbolAddress((void**)&h, g_h);
    int* degPtr = nullptr;
    cudaGetSymbolAddress((void**)&degPtr, g_deg);
    float* w12 = nullptr;
    cudaGetSymbolAddress((void**)&w12, g_W12);

    // one-time streams + events (same DAG captured every call)
    static cudaStream_t s_side = nullptr, s_mlp = nullptr;
    static cudaEvent_t ev_fork = nullptr, ev_join = nullptr;
    static cudaEvent_t ev_agg = nullptr, ev_g3 = nullptr;
    if (s_side == nullptr) {
        cudaStreamCreateWithFlags(&s_side, cudaStreamNonBlocking);
        cudaStreamCreateWithFlags(&s_mlp, cudaStreamNonBlocking);
        cudaEventCreateWithFlags(&ev_fork, cudaEventDisableTiming);
        cudaEventCreateWithFlags(&ev_join, cudaEventDisableTiming);
        cudaEventCreateWithFlags(&ev_agg, cudaEventDisableTiming);
        cudaEventCreateWithFlags(&ev_g3, cudaEventDisableTiming);
    }

    const int M = NN;
    const int MBLK = (M + 127) / 128;

    // fork: CSR build + W12 prep on side stream, concurrent with GEMM1
    cudaEventRecord(ev_fork, 0);
    cudaStreamWaitEvent(s_side, ev_fork, 0);

    prep_w12<<<(HID * OUT_CH + 255) / 256, 256, 0, s_side>>>(W1, W2);
    cudaMemsetAsync(degPtr, 0, NN * sizeof(int), s_side);
    hist_kernel<<<1024, 256, 0, s_side>>>(dst);
    scan_partial_kernel<<<NCHK, 256, 0, s_side>>>();
    scan_chunks_kernel<<<1, 128, 0, s_side>>>();
    scan_write_kernel<<<NCHK, 256, 0, s_side>>>();
    fill_kernel<<<1024, 256, 0, s_side>>>(src, dst);
    cudaEventRecord(ev_join, s_side);

    // main stream: GEMM1 (independent of CSR build)
    sgemm_kernel<IN_CH, HID, true><<<MBLK, 256>>>(x, Wg, nullptr, h, M);

    // join: agg needs both GEMM1 (h) and CSR (row_off/csr_src)
    cudaStreamWaitEvent(0, ev_join, 0);

    // agg (monolithic, main stream)
    agg_kernel<<<(NN * 32 + 255) / 256, 256>>>(bg, out1);
    cudaEventRecord(ev_agg, 0);

    // GEMM3 on s_mlp (reads out1 via W12) concurrent with GEMM2 on main:
    // independent kernels; work scheduler fills each other's tail waves.
    cudaStreamWaitEvent(s_mlp, ev_agg, 0);
    sgemm_kernel<HID, OUT_CH, false><<<MBLK, 256, 0, s_mlp>>>(out1, w12, out3, nullptr, M);
    cudaEventRecord(ev_g3, s_mlp);

    sgemm_kernel<HID, HID, false><<<MBLK, 256>>>(out1, W1, out2, nullptr, M);

    cudaStreamWaitEvent(0, ev_g3, 0);
}